// round 16
// baseline (speedup 1.0000x reference)
#include <cuda_runtime.h>
#include <cuda_fp16.h>
#include <math_constants.h>

#define NN 50000
#define EE 800000
#define DD 128
#define ET (EE + NN)
#define NB ((NN + 255) / 256)
#define BN_EPS 1e-12f
#define SLOPE 0.2f

#define LDH 136
#define SMEM_X_BYTES (128 * LDH * 2)
#define SMEM_GEMM_BYTES (2 * SMEM_X_BYTES + 256 * 4)

// ---------------- scratch ----------------
__device__ __align__(16) float  g_h  [NN * DD];  // h = x@W, fp32 (agg is issue-bound, not BW-bound)
__device__ __align__(16) __half g_x1h[NN * DD];  // layer-1 output, fp16 (gemm staging input)
__device__ float g_hs[NN];
__device__ float g_hd[NN];
__device__ int   g_rowoff[NN + 1];
__device__ int   g_eoff[EE];
__device__ int   g_csr[ET];

struct CsrState {
    int cnt[NN];
    unsigned long long st[NB];
};
__device__ CsrState g_cs;

// ---------------- mma helpers ----------------
__device__ __forceinline__ unsigned smem_u32(const void* p) {
    return (unsigned)__cvta_generic_to_shared(p);
}
__device__ __forceinline__ void ldmA(unsigned addr, unsigned& a0, unsigned& a1,
                                     unsigned& a2, unsigned& a3) {
    asm volatile("ldmatrix.sync.aligned.m8n8.x4.shared.b16 {%0,%1,%2,%3}, [%4];"
                 : "=r"(a0), "=r"(a1), "=r"(a2), "=r"(a3) : "r"(addr));
}
__device__ __forceinline__ void ldmBT(unsigned addr, unsigned& b0, unsigned& b1) {
    asm volatile("ldmatrix.sync.aligned.m8n8.x2.trans.shared.b16 {%0,%1}, [%2];"
                 : "=r"(b0), "=r"(b1) : "r"(addr));
}
__device__ __forceinline__ void mma16816(float& d0, float& d1, float& d2, float& d3,
                                         unsigned a0, unsigned a1, unsigned a2, unsigned a3,
                                         unsigned b0, unsigned b1) {
    asm volatile("mma.sync.aligned.m16n8k16.row.col.f32.f16.f16.f32 "
                 "{%0,%1,%2,%3}, {%4,%5,%6,%7}, {%8,%9}, {%0,%1,%2,%3};"
                 : "+f"(d0), "+f"(d1), "+f"(d2), "+f"(d3)
                 : "r"(a0), "r"(a1), "r"(a2), "r"(a3), "r"(b0), "r"(b1));
}

// ============ GEMM via HMMA + fused attention dots; fp32 H out ============
template<bool HALF_IN>
__global__ __launch_bounds__(256) void gemm_dots_kernel(
    const void* __restrict__ Xv, const float* __restrict__ W,
    float* __restrict__ H,
    const float* __restrict__ asrc, const float* __restrict__ adst)
{
    extern __shared__ char smem[];
    __half* sX = (__half*)smem;
    __half* sW = (__half*)(smem + SMEM_X_BYTES);
    float*  sA = (float*) (smem + 2 * SMEM_X_BYTES);

    const int tid  = threadIdx.x;
    const int wid  = tid >> 5;
    const int lane = tid & 31;
    const int row0 = blockIdx.x * 128;

    if (HALF_IN) {
        const __half* X = (const __half*)Xv;
#pragma unroll
        for (int it = 0; it < 8; it++) {
            int e  = it * 256 + tid;
            int r  = e >> 4, c8 = e & 15;
            int gr = row0 + r;
            uint4 v = make_uint4(0u, 0u, 0u, 0u);
            if (gr < NN) v = *(const uint4*)&X[(size_t)gr * 128 + c8 * 8];
            *(uint4*)&sX[r * LDH + c8 * 8] = v;
        }
    } else {
        const float* X = (const float*)Xv;
#pragma unroll
        for (int it = 0; it < 16; it++) {
            int e  = it * 256 + tid;
            int r  = e >> 5, c4 = e & 31;
            int gr = row0 + r;
            float4 v = (gr < NN) ? *(const float4*)&X[(size_t)gr * 128 + c4 * 4]
                                 : make_float4(0.f, 0.f, 0.f, 0.f);
            __half2 h0 = __floats2half2_rn(v.x, v.y);
            __half2 h1 = __floats2half2_rn(v.z, v.w);
            *(uint2*)&sX[r * LDH + c4 * 4] = make_uint2(*(unsigned*)&h0, *(unsigned*)&h1);
        }
    }
#pragma unroll
    for (int it = 0; it < 16; it++) {
        int e = it * 256 + tid;
        int k = e >> 5, c4 = e & 31;
        float4 v = *(const float4*)&W[(size_t)k * 128 + c4 * 4];
        __half2 h0 = __floats2half2_rn(v.x, v.y);
        __half2 h1 = __floats2half2_rn(v.z, v.w);
        *(uint2*)&sW[k * LDH + c4 * 4] = make_uint2(*(unsigned*)&h0, *(unsigned*)&h1);
    }
    sA[tid] = (tid < 128) ? asrc[tid] : adst[tid - 128];
    __syncthreads();

    const int r0 = wid * 16;
    float d[16][4];
#pragma unroll
    for (int nt = 0; nt < 16; nt++)
#pragma unroll
        for (int j = 0; j < 4; j++) d[nt][j] = 0.f;

    unsigned aBase = smem_u32(&sX[(r0 + (lane & 15)) * LDH + 8 * (lane >> 4)]);
    unsigned wBase = smem_u32(sW);

#pragma unroll
    for (int k = 0; k < 8; k++) {
        unsigned a0, a1, a2, a3;
        ldmA(aBase + (16 * k) * 2, a0, a1, a2, a3);
        unsigned bRow = wBase + ((16 * k + (lane & 15)) * LDH) * 2;
#pragma unroll
        for (int nt = 0; nt < 16; nt++) {
            unsigned b0, b1;
            ldmBT(bRow + nt * 8 * 2, b0, b1);
            mma16816(d[nt][0], d[nt][1], d[nt][2], d[nt][3], a0, a1, a2, a3, b0, b1);
        }
    }

    const int qr   = lane >> 2;
    const int qc   = (lane & 3) * 2;
    const int rowA = row0 + r0 + qr;
    const int rowB = rowA + 8;
    float psA = 0.f, pdA = 0.f, psB = 0.f, pdB = 0.f;

#pragma unroll
    for (int nt = 0; nt < 16; nt++) {
        int c = nt * 8 + qc;
        float2 av = *(float2*)&sA[c];
        float2 bv = *(float2*)&sA[128 + c];
        psA += d[nt][0] * av.x + d[nt][1] * av.y;
        pdA += d[nt][0] * bv.x + d[nt][1] * bv.y;
        psB += d[nt][2] * av.x + d[nt][3] * av.y;
        pdB += d[nt][2] * bv.x + d[nt][3] * bv.y;
        if (rowA < NN)
            *(float2*)&H[(size_t)rowA * 128 + c] = make_float2(d[nt][0], d[nt][1]);
        if (rowB < NN)
            *(float2*)&H[(size_t)rowB * 128 + c] = make_float2(d[nt][2], d[nt][3]);
    }
#pragma unroll
    for (int o = 1; o <= 2; o <<= 1) {
        psA += __shfl_xor_sync(0xffffffffu, psA, o);
        pdA += __shfl_xor_sync(0xffffffffu, pdA, o);
        psB += __shfl_xor_sync(0xffffffffu, psB, o);
        pdB += __shfl_xor_sync(0xffffffffu, pdB, o);
    }
    if ((lane & 3) == 0) {
        if (rowA < NN) { g_hs[rowA] = psA; g_hd[rowA] = pdA; }
        if (rowB < NN) { g_hs[rowB] = psB; g_hd[rowB] = pdB; }
    }
}

// ================= CSR build =================
__global__ __launch_bounds__(256) void csr_hist_kernel(const int* __restrict__ edst)
{
    int t = blockIdx.x * blockDim.x + threadIdx.x;
    if (t < EE) g_eoff[t] = atomicAdd(&g_cs.cnt[edst[t]], 1);
}

__device__ __forceinline__ int block_incl_scan_256(int v, int tid)
{
    int lane = tid & 31, w = tid >> 5;
#pragma unroll
    for (int o = 1; o < 32; o <<= 1) {
        int n = __shfl_up_sync(0xffffffffu, v, o);
        if (lane >= o) v += n;
    }
    __shared__ int wsum[8];
    if (lane == 31) wsum[w] = v;
    __syncthreads();
    if (tid < 8) {
        int x = wsum[tid];
#pragma unroll
        for (int o = 1; o < 8; o <<= 1) {
            int n = __shfl_up_sync(0xffu, x, o);
            if (tid >= o) x += n;
        }
        wsum[tid] = x;
    }
    __syncthreads();
    if (w > 0) v += wsum[w - 1];
    return v;
}

// decoupled lookback scan (waits only on EARLIER blocks -> co-residency safe)
__global__ __launch_bounds__(256) void scan_kernel()
{
    const int t = threadIdx.x, b = blockIdx.x;
    const int i = b * 256 + t;
    int v = (i < NN) ? g_cs.cnt[i] + 1 : 0;     // +1: self-loop slot
    int incl = block_incl_scan_256(v, t);

    __shared__ int s_agg;
    __shared__ int s_prefix;
    if (t == 255) s_agg = incl;
    if (b == 0 && t == 0) g_rowoff[0] = 0;
    __syncthreads();

    if (t == 0) {
        int agg = s_agg;
        if (b == 0) {
            *(volatile unsigned long long*)&g_cs.st[0] = (2ull << 32) | (unsigned)agg;
            s_prefix = 0;
        } else {
            *(volatile unsigned long long*)&g_cs.st[b] = (1ull << 32) | (unsigned)agg;
            int sum = 0;
            for (int p = b - 1; p >= 0; p--) {
                unsigned long long st;
                do { st = *(volatile unsigned long long*)&g_cs.st[p]; }
                while ((st >> 32) == 0ull);
                sum += (int)(st & 0xffffffffull);
                if ((st >> 32) == 2ull) break;
            }
            s_prefix = sum;
            *(volatile unsigned long long*)&g_cs.st[b] = (2ull << 32) | (unsigned)(sum + agg);
        }
    }
    __syncthreads();
    if (i < NN) g_rowoff[i + 1] = incl + s_prefix;
}

__global__ __launch_bounds__(256) void csr_scatter_kernel(
    const int* __restrict__ esrc, const int* __restrict__ edst)
{
    int t = blockIdx.x * blockDim.x + threadIdx.x;
    if (t >= ET) return;
    if (t < EE) {
        int d = edst[t];
        g_csr[g_rowoff[d] + 1 + g_eoff[t]] = esrc[t];
    } else {
        int n = t - EE;
        g_csr[g_rowoff[n]] = n;      // self loop in slot 0
    }
}

// ========== fused softmax-aggregate + bias + BN + ReLU (fp32 gather) ==========
template<bool HALF_OUT>
__global__ __launch_bounds__(256) void agg_kernel(
    void* __restrict__ outv,
    const float* __restrict__ bias,  const float* __restrict__ gamma,
    const float* __restrict__ beta,  const float* __restrict__ mean,
    const float* __restrict__ var)
{
    __shared__ float s_sc[128];
    __shared__ float s_sh[128];
    {
        int t = threadIdx.x;
        if (t < 128) {
            float sc = gamma[t] * rsqrtf(var[t] + BN_EPS);
            s_sc[t] = sc;
            s_sh[t] = (bias[t] - mean[t]) * sc + beta[t];
        }
    }
    __syncthreads();

    int node = (int)(((size_t)blockIdx.x * blockDim.x + threadIdx.x) >> 5);
    int lane = threadIdx.x & 31;
    if (node >= NN) return;

    const int off = g_rowoff[node];
    const int end = g_rowoff[node + 1];
    const float hd_d = g_hd[node];
    const float* hbase = g_h + lane * 4;   // this lane's 4 features

    float ssum = 0.f;
    float4 acc = make_float4(0.f, 0.f, 0.f, 0.f);

    for (int base = off; base < end; base += 32) {
        int rem = end - base; if (rem > 32) rem = 32;
        int s = 0; float ee = 0.f;                 // zero-pad: s=0 gather safe, ee=0 no-op
        if (lane < rem) {
            s = g_csr[base + lane];
            float e = g_hs[s] + hd_d;
            e = e > 0.f ? e : SLOPE * e;
            ee = __expf(e);                        // scores O(1..10): shift-free softmax
            ssum += ee;
        }
        int rup = (rem + 3) & ~3;                  // chunks of 4, zero-padded
        for (int j = 0; j < rup; j += 4) {
#pragma unroll
            for (int u = 0; u < 4; u++) {
                int   sj  = __shfl_sync(0xffffffffu, s,  j + u);
                float eej = __shfl_sync(0xffffffffu, ee, j + u);
                float4 pk = *(const float4*)(hbase + (size_t)sj * 128);
                acc.x += eej * pk.x; acc.y += eej * pk.y;
                acc.z += eej * pk.z; acc.w += eej * pk.w;
            }
        }
    }
#pragma unroll
    for (int o = 16; o; o >>= 1) ssum += __shfl_xor_sync(0xffffffffu, ssum, o);
    float inv = 1.f / ssum;

    float4 sc4 = *(const float4*)&s_sc[lane * 4];
    float4 sh4 = *(const float4*)&s_sh[lane * 4];
    float4 o4;
    o4.x = fmaxf(fmaf(acc.x * inv, sc4.x, sh4.x), 0.f);
    o4.y = fmaxf(fmaf(acc.y * inv, sc4.y, sh4.y), 0.f);
    o4.z = fmaxf(fmaf(acc.z * inv, sc4.z, sh4.z), 0.f);
    o4.w = fmaxf(fmaf(acc.w * inv, sc4.w, sh4.w), 0.f);

    if (HALF_OUT) {
        __half2 q0 = __floats2half2_rn(o4.x, o4.y);
        __half2 q1 = __floats2half2_rn(o4.z, o4.w);
        *(uint2*)&((__half*)outv)[(size_t)node * 128 + lane * 4] =
            make_uint2(*(unsigned*)&q0, *(unsigned*)&q1);
    } else {
        ((float4*)outv)[(size_t)node * 32 + lane] = o4;
    }
}

// ---------------- host orchestration ----------------
extern "C" void kernel_launch(void* const* d_in, const int* in_sizes, int n_in,
                              void* d_out, int out_size)
{
    const float* x     = (const float*)d_in[0];
    const int*   eidx  = (const int*)d_in[1];
    const float* Ws    = (const float*)d_in[2];
    const float* a_src = (const float*)d_in[3];
    const float* a_dst = (const float*)d_in[4];
    const float* bias  = (const float*)d_in[5];
    const float* gamma = (const float*)d_in[6];
    const float* beta  = (const float*)d_in[7];
    const float* mean  = (const float*)d_in[8];
    const float* var   = (const float*)d_in[9];
    float*       out   = (float*)d_out;

    const int* esrc = eidx;
    const int* edst = eidx + EE;

    float*  p_h;   cudaGetSymbolAddress((void**)&p_h,  g_h);
    __half* p_x1h; cudaGetSymbolAddress((void**)&p_x1h, g_x1h);
    void*   p_cs;  cudaGetSymbolAddress(&p_cs, g_cs);

    static cudaStream_t s_side = nullptr;
    static cudaEvent_t  ev_fork = nullptr, ev_join = nullptr;
    if (!s_side) {
        cudaStreamCreateWithFlags(&s_side, cudaStreamNonBlocking);
        cudaEventCreateWithFlags(&ev_fork, cudaEventDisableTiming);
        cudaEventCreateWithFlags(&ev_join, cudaEventDisableTiming);
        cudaFuncSetAttribute(gemm_dots_kernel<false>,
                             cudaFuncAttributeMaxDynamicSharedMemorySize, SMEM_GEMM_BYTES);
        cudaFuncSetAttribute(gemm_dots_kernel<true>,
                             cudaFuncAttributeMaxDynamicSharedMemorySize, SMEM_GEMM_BYTES);
    }

    // fork: gemm-0 on side stream; CSR chain on main stream
    cudaEventRecord(ev_fork, 0);
    cudaStreamWaitEvent(s_side, ev_fork, 0);
    gemm_dots_kernel<false><<<(NN + 127) / 128, 256, SMEM_GEMM_BYTES, s_side>>>(
        x, Ws, p_h, a_src, a_dst);
    cudaEventRecord(ev_join, s_side);

    cudaMemsetAsync(p_cs, 0, sizeof(CsrState));
    csr_hist_kernel<<<(EE + 255) / 256, 256>>>(edst);
    scan_kernel<<<NB, 256>>>();
    csr_scatter_kernel<<<(ET + 255) / 256, 256>>>(esrc, edst);
    cudaStreamWaitEvent(0, ev_join, 0);

    // layer 0 aggregate, then layer 1
    agg_kernel<true><<<(NN * 32 + 255) / 256, 256>>>(p_x1h, bias, gamma, beta, mean, var);
    gemm_dots_kernel<true><<<(NN + 127) / 128, 256, SMEM_GEMM_BYTES>>>(
        p_x1h, Ws + DD * DD, p_h, a_src + DD, a_dst + DD);
    agg_kernel<false><<<(NN * 32 + 255) / 256, 256>>>(out, bias + DD, gamma + DD,
                                                      beta + DD, mean + DD, var + DD);
}

// round 17
// speedup vs baseline: 1.1370x; 1.1370x over previous
#include <cuda_runtime.h>
#include <cuda_fp16.h>
#include <math_constants.h>

#define NN 50000
#define EE 800000
#define DD 128
#define ET (EE + NN)
#define NB ((NN + 255) / 256)
#define BN_EPS 1e-12f
#define SLOPE 0.2f

#define LDH 136
#define SMEM_X_BYTES (128 * LDH * 2)
#define SMEM_GEMM_BYTES (2 * SMEM_X_BYTES + 256 * 4)

// ---------------- scratch ----------------
__device__ __align__(16) __half g_h  [NN * DD];  // h = x@W, fp16 (gather path)
__device__ __align__(16) __half g_x1h[NN * DD];  // layer-1 output, fp16
__device__ float g_hs[NN];
__device__ float g_hd[NN];
__device__ int   g_rowoff[NN + 1];
__device__ int   g_eoff[EE];
__device__ int   g_csr[ET];

struct CsrState {
    int cnt[NN];
    unsigned long long st[NB];
};
__device__ CsrState g_cs;

// ---------------- mma helpers ----------------
__device__ __forceinline__ unsigned smem_u32(const void* p) {
    return (unsigned)__cvta_generic_to_shared(p);
}
__device__ __forceinline__ void ldmA(unsigned addr, unsigned& a0, unsigned& a1,
                                     unsigned& a2, unsigned& a3) {
    asm volatile("ldmatrix.sync.aligned.m8n8.x4.shared.b16 {%0,%1,%2,%3}, [%4];"
                 : "=r"(a0), "=r"(a1), "=r"(a2), "=r"(a3) : "r"(addr));
}
__device__ __forceinline__ void ldmBT(unsigned addr, unsigned& b0, unsigned& b1) {
    asm volatile("ldmatrix.sync.aligned.m8n8.x2.trans.shared.b16 {%0,%1}, [%2];"
                 : "=r"(b0), "=r"(b1) : "r"(addr));
}
__device__ __forceinline__ void mma16816(float& d0, float& d1, float& d2, float& d3,
                                         unsigned a0, unsigned a1, unsigned a2, unsigned a3,
                                         unsigned b0, unsigned b1) {
    asm volatile("mma.sync.aligned.m16n8k16.row.col.f32.f16.f16.f32 "
                 "{%0,%1,%2,%3}, {%4,%5,%6,%7}, {%8,%9}, {%0,%1,%2,%3};"
                 : "+f"(d0), "+f"(d1), "+f"(d2), "+f"(d3)
                 : "r"(a0), "r"(a1), "r"(a2), "r"(a3), "r"(b0), "r"(b1));
}

// ============ GEMM via HMMA + fused attention dots ============
template<bool HALF_IN>
__global__ __launch_bounds__(256) void gemm_dots_kernel(
    const void* __restrict__ Xv, const float* __restrict__ W,
    __half* __restrict__ H,
    const float* __restrict__ asrc, const float* __restrict__ adst)
{
    extern __shared__ char smem[];
    __half* sX = (__half*)smem;
    __half* sW = (__half*)(smem + SMEM_X_BYTES);
    float*  sA = (float*) (smem + 2 * SMEM_X_BYTES);

    const int tid  = threadIdx.x;
    const int wid  = tid >> 5;
    const int lane = tid & 31;
    const int row0 = blockIdx.x * 128;

    if (HALF_IN) {
        const __half* X = (const __half*)Xv;
#pragma unroll
        for (int it = 0; it < 8; it++) {
            int e  = it * 256 + tid;
            int r  = e >> 4, c8 = e & 15;
            int gr = row0 + r;
            uint4 v = make_uint4(0u, 0u, 0u, 0u);
            if (gr < NN) v = *(const uint4*)&X[(size_t)gr * 128 + c8 * 8];
            *(uint4*)&sX[r * LDH + c8 * 8] = v;
        }
    } else {
        const float* X = (const float*)Xv;
#pragma unroll
        for (int it = 0; it < 16; it++) {
            int e  = it * 256 + tid;
            int r  = e >> 5, c4 = e & 31;
            int gr = row0 + r;
            float4 v = (gr < NN) ? *(const float4*)&X[(size_t)gr * 128 + c4 * 4]
                                 : make_float4(0.f, 0.f, 0.f, 0.f);
            __half2 h0 = __floats2half2_rn(v.x, v.y);
            __half2 h1 = __floats2half2_rn(v.z, v.w);
            *(uint2*)&sX[r * LDH + c4 * 4] = make_uint2(*(unsigned*)&h0, *(unsigned*)&h1);
        }
    }
#pragma unroll
    for (int it = 0; it < 16; it++) {
        int e = it * 256 + tid;
        int k = e >> 5, c4 = e & 31;
        float4 v = *(const float4*)&W[(size_t)k * 128 + c4 * 4];
        __half2 h0 = __floats2half2_rn(v.x, v.y);
        __half2 h1 = __floats2half2_rn(v.z, v.w);
        *(uint2*)&sW[k * LDH + c4 * 4] = make_uint2(*(unsigned*)&h0, *(unsigned*)&h1);
    }
    sA[tid] = (tid < 128) ? asrc[tid] : adst[tid - 128];
    __syncthreads();

    const int r0 = wid * 16;
    float d[16][4];
#pragma unroll
    for (int nt = 0; nt < 16; nt++)
#pragma unroll
        for (int j = 0; j < 4; j++) d[nt][j] = 0.f;

    unsigned aBase = smem_u32(&sX[(r0 + (lane & 15)) * LDH + 8 * (lane >> 4)]);
    unsigned wBase = smem_u32(sW);

#pragma unroll
    for (int k = 0; k < 8; k++) {
        unsigned a0, a1, a2, a3;
        ldmA(aBase + (16 * k) * 2, a0, a1, a2, a3);
        unsigned bRow = wBase + ((16 * k + (lane & 15)) * LDH) * 2;
#pragma unroll
        for (int nt = 0; nt < 16; nt++) {
            unsigned b0, b1;
            ldmBT(bRow + nt * 8 * 2, b0, b1);
            mma16816(d[nt][0], d[nt][1], d[nt][2], d[nt][3], a0, a1, a2, a3, b0, b1);
        }
    }

    const int qr   = lane >> 2;
    const int qc   = (lane & 3) * 2;
    const int rowA = row0 + r0 + qr;
    const int rowB = rowA + 8;
    float psA = 0.f, pdA = 0.f, psB = 0.f, pdB = 0.f;

#pragma unroll
    for (int nt = 0; nt < 16; nt++) {
        int c = nt * 8 + qc;
        float2 av = *(float2*)&sA[c];
        float2 bv = *(float2*)&sA[128 + c];
        psA += d[nt][0] * av.x + d[nt][1] * av.y;
        pdA += d[nt][0] * bv.x + d[nt][1] * bv.y;
        psB += d[nt][2] * av.x + d[nt][3] * av.y;
        pdB += d[nt][2] * bv.x + d[nt][3] * bv.y;
        if (rowA < NN) {
            __half2 hh = __floats2half2_rn(d[nt][0], d[nt][1]);
            *(__half2*)&H[(size_t)rowA * 128 + c] = hh;
        }
        if (rowB < NN) {
            __half2 hh = __floats2half2_rn(d[nt][2], d[nt][3]);
            *(__half2*)&H[(size_t)rowB * 128 + c] = hh;
        }
    }
#pragma unroll
    for (int o = 1; o <= 2; o <<= 1) {
        psA += __shfl_xor_sync(0xffffffffu, psA, o);
        pdA += __shfl_xor_sync(0xffffffffu, pdA, o);
        psB += __shfl_xor_sync(0xffffffffu, psB, o);
        pdB += __shfl_xor_sync(0xffffffffu, pdB, o);
    }
    if ((lane & 3) == 0) {
        if (rowA < NN) { g_hs[rowA] = psA; g_hd[rowA] = pdA; }
        if (rowB < NN) { g_hs[rowB] = psB; g_hd[rowB] = pdB; }
    }
}

// ================= CSR build =================
__global__ __launch_bounds__(256) void csr_hist_kernel(const int* __restrict__ edst)
{
    int t = blockIdx.x * blockDim.x + threadIdx.x;
    if (t < EE) g_eoff[t] = atomicAdd(&g_cs.cnt[edst[t]], 1);
}

__device__ __forceinline__ int block_incl_scan_256(int v, int tid)
{
    int lane = tid & 31, w = tid >> 5;
#pragma unroll
    for (int o = 1; o < 32; o <<= 1) {
        int n = __shfl_up_sync(0xffffffffu, v, o);
        if (lane >= o) v += n;
    }
    __shared__ int wsum[8];
    if (lane == 31) wsum[w] = v;
    __syncthreads();
    if (tid < 8) {
        int x = wsum[tid];
#pragma unroll
        for (int o = 1; o < 8; o <<= 1) {
            int n = __shfl_up_sync(0xffu, x, o);
            if (tid >= o) x += n;
        }
        wsum[tid] = x;
    }
    __syncthreads();
    if (w > 0) v += wsum[w - 1];
    return v;
}

// decoupled lookback scan (waits only on EARLIER blocks -> co-residency safe)
__global__ __launch_bounds__(256) void scan_kernel()
{
    const int t = threadIdx.x, b = blockIdx.x;
    const int i = b * 256 + t;
    int v = (i < NN) ? g_cs.cnt[i] + 1 : 0;     // +1: self-loop slot
    int incl = block_incl_scan_256(v, t);

    __shared__ int s_agg;
    __shared__ int s_prefix;
    if (t == 255) s_agg = incl;
    if (b == 0 && t == 0) g_rowoff[0] = 0;
    __syncthreads();

    if (t == 0) {
        int agg = s_agg;
        if (b == 0) {
            *(volatile unsigned long long*)&g_cs.st[0] = (2ull << 32) | (unsigned)agg;
            s_prefix = 0;
        } else {
            *(volatile unsigned long long*)&g_cs.st[b] = (1ull << 32) | (unsigned)agg;
            int sum = 0;
            for (int p = b - 1; p >= 0; p--) {
                unsigned long long st;
                do { st = *(volatile unsigned long long*)&g_cs.st[p]; }
                while ((st >> 32) == 0ull);
                sum += (int)(st & 0xffffffffull);
                if ((st >> 32) == 2ull) break;
            }
            s_prefix = sum;
            *(volatile unsigned long long*)&g_cs.st[b] = (2ull << 32) | (unsigned)(sum + agg);
        }
    }
    __syncthreads();
    if (i < NN) g_rowoff[i + 1] = incl + s_prefix;
}

__global__ __launch_bounds__(256) void csr_scatter_kernel(
    const int* __restrict__ esrc, const int* __restrict__ edst)
{
    int t = blockIdx.x * blockDim.x + threadIdx.x;
    if (t >= ET) return;
    if (t < EE) {
        int d = edst[t];
        g_csr[g_rowoff[d] + 1 + g_eoff[t]] = esrc[t];
    } else {
        int n = t - EE;
        g_csr[g_rowoff[n]] = n;      // self loop in slot 0
    }
}

// ========== fused softmax-aggregate + bias + BN + ReLU ==========
// broadcast (src, weight) via warp smem stage: 1 STS.64/lane/chunk + LDS.128 reads
template<bool HALF_OUT>
__global__ __launch_bounds__(256) void agg_kernel(
    void* __restrict__ outv,
    const float* __restrict__ bias,  const float* __restrict__ gamma,
    const float* __restrict__ beta,  const float* __restrict__ mean,
    const float* __restrict__ var)
{
    __shared__ float s_sc[128];
    __shared__ float s_sh[128];
    __shared__ __align__(16) float2 s_pair[8][32];   // per-warp (src, ee) stage
    {
        int t = threadIdx.x;
        if (t < 128) {
            float sc = gamma[t] * rsqrtf(var[t] + BN_EPS);
            s_sc[t] = sc;
            s_sh[t] = (bias[t] - mean[t]) * sc + beta[t];
        }
    }
    __syncthreads();

    int node = (int)(((size_t)blockIdx.x * blockDim.x + threadIdx.x) >> 5);
    int lane = threadIdx.x & 31;
    if (node >= NN) return;

    float2* wp = &s_pair[(threadIdx.x >> 5)][0];

    const int off = g_rowoff[node];
    const int end = g_rowoff[node + 1];
    const float hd_d = g_hd[node];

    float ssum = 0.f;
    float4 acc = make_float4(0.f, 0.f, 0.f, 0.f);

    for (int base = off; base < end; base += 32) {
        int rem = end - base; if (rem > 32) rem = 32;
        int s = 0; float ee = 0.f;                 // zero-pad: s=0 gather safe, ee=0 no-op
        if (lane < rem) {
            s = g_csr[base + lane];
            float e = g_hs[s] + hd_d;
            e = e > 0.f ? e : SLOPE * e;
            ee = __expf(e);                        // scores O(1..10): shift-free softmax
            ssum += ee;
        }
        wp[lane] = make_float2(__int_as_float(s), ee);
        __syncwarp();

        int rup = (rem + 3) & ~3;                  // chunks of 4, zero-padded
        for (int j = 0; j < rup; j += 4) {
            float4 p0 = *(const float4*)&wp[j];        // edges j, j+1
            float4 p1 = *(const float4*)&wp[j + 2];    // edges j+2, j+3
#pragma unroll
            for (int u = 0; u < 4; u++) {
                int   sj  = __float_as_int(u == 0 ? p0.x : u == 1 ? p0.z : u == 2 ? p1.x : p1.z);
                float eej =                (u == 0 ? p0.y : u == 1 ? p0.w : u == 2 ? p1.y : p1.w);
                uint2 pk = *(const uint2*)&g_h[(size_t)sj * 128 + lane * 4];
                float2 f0 = __half22float2(*(__half2*)&pk.x);
                float2 f1 = __half22float2(*(__half2*)&pk.y);
                acc.x += eej * f0.x; acc.y += eej * f0.y;
                acc.z += eej * f1.x; acc.w += eej * f1.y;
            }
        }
        __syncwarp();                              // WAR: next chunk rewrites wp
    }
#pragma unroll
    for (int o = 16; o; o >>= 1) ssum += __shfl_xor_sync(0xffffffffu, ssum, o);
    float inv = 1.f / ssum;

    float4 sc4 = *(const float4*)&s_sc[lane * 4];
    float4 sh4 = *(const float4*)&s_sh[lane * 4];
    float4 o4;
    o4.x = fmaxf(fmaf(acc.x * inv, sc4.x, sh4.x), 0.f);
    o4.y = fmaxf(fmaf(acc.y * inv, sc4.y, sh4.y), 0.f);
    o4.z = fmaxf(fmaf(acc.z * inv, sc4.z, sh4.z), 0.f);
    o4.w = fmaxf(fmaf(acc.w * inv, sc4.w, sh4.w), 0.f);

    if (HALF_OUT) {
        __half2 q0 = __floats2half2_rn(o4.x, o4.y);
        __half2 q1 = __floats2half2_rn(o4.z, o4.w);
        *(uint2*)&((__half*)outv)[(size_t)node * 128 + lane * 4] =
            make_uint2(*(unsigned*)&q0, *(unsigned*)&q1);
    } else {
        ((float4*)outv)[(size_t)node * 32 + lane] = o4;
    }
}

// ---------------- host orchestration ----------------
extern "C" void kernel_launch(void* const* d_in, const int* in_sizes, int n_in,
                              void* d_out, int out_size)
{
    const float* x     = (const float*)d_in[0];
    const int*   eidx  = (const int*)d_in[1];
    const float* Ws    = (const float*)d_in[2];
    const float* a_src = (const float*)d_in[3];
    const float* a_dst = (const float*)d_in[4];
    const float* bias  = (const float*)d_in[5];
    const float* gamma = (const float*)d_in[6];
    const float* beta  = (const float*)d_in[7];
    const float* mean  = (const float*)d_in[8];
    const float* var   = (const float*)d_in[9];
    float*       out   = (float*)d_out;

    const int* esrc = eidx;
    const int* edst = eidx + EE;

    __half* p_h;   cudaGetSymbolAddress((void**)&p_h,  g_h);
    __half* p_x1h; cudaGetSymbolAddress((void**)&p_x1h, g_x1h);
    void*   p_cs;  cudaGetSymbolAddress(&p_cs, g_cs);

    static cudaStream_t s_side = nullptr;
    static cudaEvent_t  ev_fork = nullptr, ev_join = nullptr;
    if (!s_side) {
        cudaStreamCreateWithFlags(&s_side, cudaStreamNonBlocking);
        cudaEventCreateWithFlags(&ev_fork, cudaEventDisableTiming);
        cudaEventCreateWithFlags(&ev_join, cudaEventDisableTiming);
        cudaFuncSetAttribute(gemm_dots_kernel<false>,
                             cudaFuncAttributeMaxDynamicSharedMemorySize, SMEM_GEMM_BYTES);
        cudaFuncSetAttribute(gemm_dots_kernel<true>,
                             cudaFuncAttributeMaxDynamicSharedMemorySize, SMEM_GEMM_BYTES);
    }

    // fork: gemm-0 on side stream; CSR chain on main stream
    cudaEventRecord(ev_fork, 0);
    cudaStreamWaitEvent(s_side, ev_fork, 0);
    gemm_dots_kernel<false><<<(NN + 127) / 128, 256, SMEM_GEMM_BYTES, s_side>>>(
        x, Ws, p_h, a_src, a_dst);
    cudaEventRecord(ev_join, s_side);

    cudaMemsetAsync(p_cs, 0, sizeof(CsrState));
    csr_hist_kernel<<<(EE + 255) / 256, 256>>>(edst);
    scan_kernel<<<NB, 256>>>();
    csr_scatter_kernel<<<(ET + 255) / 256, 256>>>(esrc, edst);
    cudaStreamWaitEvent(0, ev_join, 0);

    // layer 0 aggregate, then layer 1
    agg_kernel<true><<<(NN * 32 + 255) / 256, 256>>>(p_x1h, bias, gamma, beta, mean, var);
    gemm_dots_kernel<true><<<(NN + 127) / 128, 256, SMEM_GEMM_BYTES>>>(
        p_x1h, Ws + DD * DD, p_h, a_src + DD, a_dst + DD);
    agg_kernel<false><<<(NN * 32 + 255) / 256, 256>>>(out, bias + DD, gamma + DD,
                                                      beta + DD, mean + DD, var + DD);
}